// round 1
// baseline (speedup 1.0000x reference)
#include <cuda_runtime.h>
#include <cuda_bf16.h>
#include <cstdint>
#include <cstddef>

// Problem constants
#define BATCH   32
#define TSTEPS  2048
#define INDIM   256
#define HDIM    256
#define GDIM    768            // 3*H
#define OUTDIM  256

// Scratch for xg = x @ W_i + bias : (B*T, 3H) fp32 = 192 MB
__device__ float g_xg[(size_t)BATCH * TSTEPS * GDIM];

// ---------------------------------------------------------------------------
// Helpers
// ---------------------------------------------------------------------------
__device__ __forceinline__ uint32_t smem_u32(const void* p) {
    uint32_t a;
    asm("{ .reg .u64 t; cvta.to.shared.u64 t, %1; cvt.u32.u64 %0, t; }"
        : "=r"(a) : "l"(p));
    return a;
}

__device__ __forceinline__ void cluster_sync_() {
    asm volatile("barrier.cluster.arrive.aligned;" ::: "memory");
    asm volatile("barrier.cluster.wait.aligned;" ::: "memory");
}

__device__ __forceinline__ float sigmoid_(float x) {
    return 1.0f / (1.0f + __expf(-x));
}

// ---------------------------------------------------------------------------
// Kernel 1: xg = x @ W_i + bias    (M=65536, N=768, K=256)  fp32 tiled SGEMM
// BM=128, BN=64, BK=16, 256 threads, each thread computes 8x4 outputs.
// ---------------------------------------------------------------------------
__global__ __launch_bounds__(256)
void gemm_xg_kernel(const float* __restrict__ X,
                    const float* __restrict__ Wi,
                    const float* __restrict__ bias)
{
    __shared__ __align__(16) float As[16][128];   // transposed A tile
    __shared__ __align__(16) float Bs[16][64];

    const int bm = blockIdx.x * 128;
    const int bn = blockIdx.y * 64;
    const int tid = threadIdx.x;
    const int tx = tid & 15;       // N direction (4 cols each)
    const int ty = tid >> 4;       // M direction (8 rows each)

    float acc[8][4];
#pragma unroll
    for (int i = 0; i < 8; ++i)
#pragma unroll
        for (int j = 0; j < 4; ++j) acc[i][j] = 0.0f;

    for (int k0 = 0; k0 < INDIM; k0 += 16) {
        // Load A tile 128x16 (2 float4 per thread), store transposed
#pragma unroll
        for (int q = 0; q < 2; ++q) {
            int f   = q * 256 + tid;
            int row = f >> 2;
            int k4  = (f & 3) << 2;
            float4 v = *reinterpret_cast<const float4*>(
                X + (size_t)(bm + row) * INDIM + k0 + k4);
            As[k4 + 0][row] = v.x;
            As[k4 + 1][row] = v.y;
            As[k4 + 2][row] = v.z;
            As[k4 + 3][row] = v.w;
        }
        // Load B tile 16x64 (1 float4 per thread)
        {
            int kr = tid >> 4;
            int c4 = (tid & 15) << 2;
            float4 v = *reinterpret_cast<const float4*>(
                Wi + (size_t)(k0 + kr) * GDIM + bn + c4);
            *reinterpret_cast<float4*>(&Bs[kr][c4]) = v;
        }
        __syncthreads();

#pragma unroll
        for (int kk = 0; kk < 16; ++kk) {
            float4 a0 = *reinterpret_cast<const float4*>(&As[kk][ty * 8]);
            float4 a1 = *reinterpret_cast<const float4*>(&As[kk][ty * 8 + 4]);
            float4 bv = *reinterpret_cast<const float4*>(&Bs[kk][tx * 4]);
            float a[8] = {a0.x, a0.y, a0.z, a0.w, a1.x, a1.y, a1.z, a1.w};
            float bb[4] = {bv.x, bv.y, bv.z, bv.w};
#pragma unroll
            for (int i = 0; i < 8; ++i)
#pragma unroll
                for (int j = 0; j < 4; ++j)
                    acc[i][j] = fmaf(a[i], bb[j], acc[i][j]);
        }
        __syncthreads();
    }

    float4 bv = *reinterpret_cast<const float4*>(bias + bn + tx * 4);
#pragma unroll
    for (int i = 0; i < 8; ++i) {
        int row = bm + ty * 8 + i;
        float4 o;
        o.x = acc[i][0] + bv.x;
        o.y = acc[i][1] + bv.y;
        o.z = acc[i][2] + bv.z;
        o.w = acc[i][3] + bv.w;
        *reinterpret_cast<float4*>(g_xg + (size_t)row * GDIM + bn + tx * 4) = o;
    }
}

// ---------------------------------------------------------------------------
// Kernel 2: the GRU recurrence.
// Grid = 128 CTAs, cluster of 4 CTAs per batch row. 384 threads/CTA.
// Each CTA owns 192 W_h columns (its 64-wide H-slice of r,z,n gates),
// held entirely in registers: 2 threads per column, 128 K-values each.
// Per step: dot products -> gate math on 64 threads -> DSMEM broadcast of
// the h chunk to all 4 CTAs (double-buffered) -> barrier.cluster.
// ---------------------------------------------------------------------------
__global__ __launch_bounds__(384, 1) __cluster_dims__(4, 1, 1)
void gru_rec_kernel(const float* __restrict__ Wh,
                    float* __restrict__ states)
{
    __shared__ __align__(16) float h_sm[2][HDIM];
    __shared__ float g_sm[192];

    uint32_t crank;
    asm("mov.u32 %0, %%cluster_ctarank;" : "=r"(crank));
    const int b      = blockIdx.x >> 2;
    const int tid    = threadIdx.x;
    const int half   = tid & 1;       // which K half (0:[0,128) 1:[128,256))
    const int pairId = tid >> 1;      // 0..191 -> column within CTA slice
    const int gate   = pairId >> 6;   // 0..2
    const int j      = pairId & 63;   // H index within chunk
    const int col    = gate * HDIM + (int)crank * 64 + j;  // global W_h column

    // Load this thread's W_h half-column into registers (one-time, L2-resident)
    float Wreg[128];
    {
        const float* wp = Wh + (size_t)(half * 128) * GDIM + col;
#pragma unroll
        for (int i = 0; i < 128; ++i) Wreg[i] = wp[(size_t)i * GDIM];
    }

    // h0 = 0 in both buffers
    if (tid < HDIM) { h_sm[0][tid] = 0.0f; h_sm[1][tid] = 0.0f; }
    __syncthreads();
    cluster_sync_();   // all buffers zeroed cluster-wide before any DSMEM write

    const float* xgp = g_xg + (size_t)b * TSTEPS * GDIM + col;
    float xg_val = (half == 0) ? xgp[0] : 0.0f;

    const size_t st_base = (size_t)b * 4 * TSTEPS * HDIM;
    const uint32_t h_local0 = smem_u32(&h_sm[0][0]);
    const uint32_t h_local1 = smem_u32(&h_sm[1][0]);

    int cur = 0;
    for (int t = 0; t < TSTEPS; ++t) {
        // ---- dot(h, Wcol) over this thread's K half ----
        const float* h_cur = &h_sm[cur][half * 128];
        float a0 = 0.f, a1 = 0.f, a2 = 0.f, a3 = 0.f;
#pragma unroll
        for (int i = 0; i < 128; i += 4) {
            float4 hv = *reinterpret_cast<const float4*>(h_cur + i);
            a0 = fmaf(Wreg[i + 0], hv.x, a0);
            a1 = fmaf(Wreg[i + 1], hv.y, a1);
            a2 = fmaf(Wreg[i + 2], hv.z, a2);
            a3 = fmaf(Wreg[i + 3], hv.w, a3);
        }
        float s = (a0 + a1) + (a2 + a3);
        s += __shfl_xor_sync(0xffffffffu, s, 1);   // combine the two K halves

        if (half == 0) {
            g_sm[pairId] = xg_val + s;
            if (t + 1 < TSTEPS)                    // prefetch next step's xg
                xg_val = xgp[(size_t)(t + 1) * GDIM];
        }
        __syncthreads();

        // ---- gate math + state writes + h broadcast (64 threads) ----
        if (tid < 64) {
            const int jj = tid;
            float rg = g_sm[jj];
            float zg = g_sm[64 + jj];
            float gg = g_sm[128 + jj];
            float r  = sigmoid_(rg);
            float z  = sigmoid_(zg);
            float n  = tanhf(fmaf(r, gg, gg));     // tanh(gn + r*gn)
            float h_old = h_sm[cur][(int)crank * 64 + jj];
            float hn = fmaf(z, h_old - n, n);      // (1-z)n + z h

            float* sp = states + st_base + (size_t)t * HDIM + (int)crank * 64 + jj;
            sp[0]                              = hn;  // plane 0: h_new
            sp[(size_t)TSTEPS * HDIM]          = r;   // plane 1: r
            sp[(size_t)2 * TSTEPS * HDIM]      = z;   // plane 2: z
            sp[(size_t)3 * TSTEPS * HDIM]      = n;   // plane 3: n

            // write h chunk into next buffer of all 4 cluster CTAs
            uint32_t laddr = ((cur ^ 1) ? h_local1 : h_local0)
                             + ((uint32_t)crank * 64 + (uint32_t)jj) * 4u;
#pragma unroll
            for (int rk = 0; rk < 4; ++rk) {
                uint32_t raddr;
                asm volatile("mapa.shared::cluster.u32 %0, %1, %2;"
                             : "=r"(raddr) : "r"(laddr), "r"(rk));
                asm volatile("st.shared::cluster.f32 [%0], %1;"
                             :: "r"(raddr), "f"(hn) : "memory");
            }
        }

        cluster_sync_();   // release h writes, acquire peers' writes
        cur ^= 1;
    }
}

// ---------------------------------------------------------------------------
// Kernel 3: output = h_last @ fc_w + fc_b   (32 x 256, K=256) — tiny
// h_last = states[b][0][T-1][:]
// ---------------------------------------------------------------------------
__global__ __launch_bounds__(256)
void fc_kernel(const float* __restrict__ states,
               const float* __restrict__ fc_w,
               const float* __restrict__ fc_b,
               float* __restrict__ out)
{
    const int b = blockIdx.x;
    const int o = threadIdx.x;
    const float* h = states + (((size_t)b * 4 + 0) * TSTEPS + (TSTEPS - 1)) * HDIM;
    float a0 = 0.f, a1 = 0.f, a2 = 0.f, a3 = 0.f;
#pragma unroll 8
    for (int k = 0; k < HDIM; k += 4) {
        a0 = fmaf(h[k + 0], fc_w[(size_t)(k + 0) * OUTDIM + o], a0);
        a1 = fmaf(h[k + 1], fc_w[(size_t)(k + 1) * OUTDIM + o], a1);
        a2 = fmaf(h[k + 2], fc_w[(size_t)(k + 2) * OUTDIM + o], a2);
        a3 = fmaf(h[k + 3], fc_w[(size_t)(k + 3) * OUTDIM + o], a3);
    }
    out[(size_t)b * OUTDIM + o] = (a0 + a1) + (a2 + a3) + fc_b[o];
}

// ---------------------------------------------------------------------------
// Launch
// ---------------------------------------------------------------------------
extern "C" void kernel_launch(void* const* d_in, const int* in_sizes, int n_in,
                              void* d_out, int out_size)
{
    const float* x    = (const float*)d_in[0];
    const float* Wi   = (const float*)d_in[1];
    const float* Wh   = (const float*)d_in[2];
    const float* bias = (const float*)d_in[3];
    const float* fcw  = (const float*)d_in[4];
    const float* fcb  = (const float*)d_in[5];

    float* out    = (float*)d_out;                 // (32, 256)
    float* states = out + (size_t)BATCH * OUTDIM;  // (32, 4, 2048, 256)

    dim3 ggrid((BATCH * TSTEPS) / 128, GDIM / 64);
    gemm_xg_kernel<<<ggrid, 256>>>(x, Wi, bias);

    gru_rec_kernel<<<BATCH * 4, 384>>>(Wh, states);

    fc_kernel<<<BATCH, 256>>>(states, fcw, fcb, out);
}